// round 7
// baseline (speedup 1.0000x reference)
#include <cuda_runtime.h>
#include <cuda_bf16.h>

// out[h] = sum_n ne_nodes[n, h]  (reference's [N,1] softmax == 1 -> MLP dead)
// 200000x256 fp32 column sum, ~205 MB HBM, DRAM-bound.
//
// R6 lesson: tier-B chunks stalled -- blocking atomic grab + 2 syncs between
// one 8-load burst and the next meant ~zero loads in flight most of each
// tier-B cycle. R7: pipeline the grab under the in-flight loads (issue loads,
// grab next chunk, THEN consume loads), double-buffer smem so each chunk
// costs a single __syncthreads. __ldcs (evict-first) on the 205MB stream.
// Partials keyed by CHUNK id, final sum in fixed chunk order -> deterministic.

#define NBLK  888               // 148 SMs * 6 CTAs, one wave @ occ 75%
#define T1    256
#define QUADS 64                // float4 column-quads (HIDDEN=256)
#define SB    2048              // tier-B chunk: 2048 float4 = 32KB
#define MAXCH 4096              // >= NBLK + NB

__device__ float4   g_partial4[QUADS * MAXCH];   // [quad][chunk]
__device__ unsigned g_work;                       // monotonic grab counter

static __device__ __forceinline__ float4 f4add(float4 a, float4 b) {
    float4 r;
    r.x = a.x + b.x; r.y = a.y + b.y; r.z = a.z + b.z; r.w = a.w + b.w;
    return r;
}

// chunk bases are multiples of 64 f4 -> thread tid owns quad tid&63 everywhere.
static __device__ __forceinline__ float4 burst8(const float4* __restrict__ b, int k) {
    float4 a0 = __ldcs(b + k);
    float4 a1 = __ldcs(b + k +  256);
    float4 a2 = __ldcs(b + k +  512);
    float4 a3 = __ldcs(b + k +  768);
    float4 a4 = __ldcs(b + k + 1024);
    float4 a5 = __ldcs(b + k + 1280);
    float4 a6 = __ldcs(b + k + 1536);
    float4 a7 = __ldcs(b + k + 1792);
    return f4add(f4add(f4add(a0, a1), f4add(a2, a3)),
                 f4add(f4add(a4, a5), f4add(a6, a7)));
}

__global__ __launch_bounds__(T1, 6) void colsum_pipe(
    const float4* __restrict__ ne4, int total4, int SA, int NB,
    float* __restrict__ out)
{
    const int tid = threadIdx.x;
    const int bid = blockIdx.x;
    const unsigned el = (unsigned)(NBLK + NB);   // grabs per epoch

    __shared__ float4   sm[2][T1];
    __shared__ unsigned s_o[2];

    // ---- tier A: static contiguous chunk, id = bid ----
    {
        const float4* base = ne4 + bid * SA;
        float4 acc = make_float4(0.f, 0.f, 0.f, 0.f);
        int k = tid;
        for (; k + 1792 < SA; k += 2048)
            acc = f4add(acc, burst8(base, k));
        for (; k < SA; k += 256)
            acc = f4add(acc, __ldcs(base + k));

        sm[0][tid] = acc;
        __syncthreads();
        if (tid < QUADS)
            g_partial4[tid * MAXCH + bid] =
                f4add(f4add(sm[0][tid],       sm[0][tid + 64]),
                      f4add(sm[0][tid + 128], sm[0][tid + 192]));
    }

    // ---- tier B: dynamic 32KB chunks, pipelined grab ----
    const int tb_base = NBLK * SA;
    if (tid == 0) {
        unsigned o0;
        asm volatile("atom.add.release.gpu.u32 %0, [%1], %2;"
                     : "=r"(o0) : "l"(&g_work), "r"(1u) : "memory");
        s_o[0] = o0;
    }
    __syncthreads();                 // broadcasts s_o[0]; tier-A sm reads done

    unsigned o  = s_o[0];
    int      pb = 1;

    for (;;) {
        const unsigned idx = o % el;
        if ((int)idx >= NB) break;                 // failing grab = arrival

        const int start = tb_base + (int)idx * SB;
        const int csz   = min(SB, total4 - start);
        const float4* cb = ne4 + start;

        float4 acc;
        if (csz == SB) {
            // issue 8 independent LDG.128 ...
            float4 a0 = __ldcs(cb + tid);
            float4 a1 = __ldcs(cb + tid +  256);
            float4 a2 = __ldcs(cb + tid +  512);
            float4 a3 = __ldcs(cb + tid +  768);
            float4 a4 = __ldcs(cb + tid + 1024);
            float4 a5 = __ldcs(cb + tid + 1280);
            float4 a6 = __ldcs(cb + tid + 1536);
            float4 a7 = __ldcs(cb + tid + 1792);
            // ... grab the NEXT chunk while they're in flight ...
            if (tid == 0) {
                unsigned on;
                asm volatile("atom.add.release.gpu.u32 %0, [%1], %2;"
                             : "=r"(on) : "l"(&g_work), "r"(1u) : "memory");
                s_o[pb] = on;
            }
            // ... then consume
            acc = f4add(f4add(f4add(a0, a1), f4add(a2, a3)),
                        f4add(f4add(a4, a5), f4add(a6, a7)));
        } else {                                   // rare ragged last chunk
            if (tid == 0) {
                unsigned on;
                asm volatile("atom.add.release.gpu.u32 %0, [%1], %2;"
                             : "=r"(on) : "l"(&g_work), "r"(1u) : "memory");
                s_o[pb] = on;
            }
            acc = make_float4(0.f, 0.f, 0.f, 0.f);
            for (int k = tid; k < csz; k += 256)
                acc = f4add(acc, __ldcs(cb + k));
        }

        sm[pb][tid] = acc;
        __syncthreads();             // publishes sm[pb] AND s_o[pb]
        if (tid < QUADS)
            g_partial4[tid * MAXCH + (NBLK + (int)idx)] =
                f4add(f4add(sm[pb][tid],       sm[pb][tid + 64]),
                      f4add(sm[pb][tid + 128], sm[pb][tid + 192]));
        o  = s_o[pb];
        pb ^= 1;
        // sm[pb_old] reads by tid<64 are ordered before the NEXT iteration's
        // __syncthreads, which precedes any rewrite of that buffer. Safe.
    }

    // ---- arrived: o is this block's failing grab ----
    const unsigned idx  = o % el;
    const unsigned rank = idx - (unsigned)NB;        // 0..NBLK-1 arrival order
    if (rank < (unsigned)(NBLK - QUADS)) return;     // early arrivals: done

    const int quad = (int)(el - 1u - idx);           // last arriver -> quad 0
    if (tid == 0) {
        const unsigned target = (o / el + 1u) * el;  // epoch boundary
        unsigned cur;
        do {
            asm volatile("ld.acquire.gpu.u32 %0, [%1];"
                         : "=r"(cur) : "l"(&g_work) : "memory");
            if (cur >= target) break;
            __nanosleep(32);
        } while (true);
    }
    __syncthreads();                                 // acquire -> whole block

    // final reduce over chunks 0..el-1 in fixed order (deterministic)
    const float4* p = g_partial4 + quad * MAXCH;
    float4 s = make_float4(0.f, 0.f, 0.f, 0.f);
    for (int i = tid; i < (int)el; i += T1)
        s = f4add(s, p[i]);

    #pragma unroll
    for (int off = 16; off > 0; off >>= 1) {
        s.x += __shfl_down_sync(0xffffffffu, s.x, off);
        s.y += __shfl_down_sync(0xffffffffu, s.y, off);
        s.z += __shfl_down_sync(0xffffffffu, s.z, off);
        s.w += __shfl_down_sync(0xffffffffu, s.w, off);
    }
    __shared__ float4 ws[T1 / 32];
    if ((tid & 31) == 0) ws[tid >> 5] = s;
    __syncthreads();
    if (tid == 0) {
        float4 r = ws[0];
        #pragma unroll
        for (int w = 1; w < T1 / 32; ++w) r = f4add(r, ws[w]);
        reinterpret_cast<float4*>(out)[quad] = r;
    }
}

extern "C" void kernel_launch(void* const* d_in, const int* in_sizes, int n_in,
                              void* d_out, int out_size)
{
    // inputs: this_node[0], relations[1], ne_nodes[2], W1[3], b1[4], W2[5], b2[6]
    const float4* ne4 = (const float4*)d_in[2];
    const int total4 = in_sizes[2] / 4;            // 12,800,000 (mult of 64)
    float* out = (float*)d_out;

    // Tier A = 7/8 of data, chunk multiple of 256 f4 (integral per-thread
    // work, 64-alignment). Tier B = remainder in 32KB chunks.
    int SA = (int)(((long long)total4 * 7 / 8) / NBLK) & ~255;
    if (SA < 256) SA = 256;
    int rem = total4 - NBLK * SA;                  // 1,660,928 here
    int NB  = (rem + SB - 1) / SB;                 // 811 (exact fit here)

    colsum_pipe<<<NBLK, T1>>>(ne4, total4, SA, NB, out);
}